// round 3
// baseline (speedup 1.0000x reference)
#include <cuda_runtime.h>
#include <cstdint>
#include <math_constants.h>

#define BATCH 16
#define NPRED 1024
#define NGT   1024
#define NP1   1025
#define NCLS  3
#define M_BASE 3
#define SEG    64          // blocks per sample
#define TPB    256         // 8 warps; warp handles 2 preds -> 16 preds/block
#define SG_BASE (M_BASE + BATCH * NP1 * NP1)

__device__ uint32_t g_keys[BATCH * NPRED];
__device__ float g_closs[BATCH * SEG];
__device__ float g_semloss[BATCH * SEG];
__device__ float g_mloss[BATCH];
__device__ int   g_samp_cnt[BATCH];   // self-resetting
__device__ int   g_done_cnt;          // self-resetting

__global__ __launch_bounds__(TPB) void fused(
    const float* __restrict__ matches,     // (B, 1025, 1025)
    const float* __restrict__ positions,   // (B, N, 2)
    const float* __restrict__ semantics,   // (B, 3, N)
    const float* __restrict__ gt_pts,      // (B, G, 2)
    const int*   __restrict__ gt_ins,
    const int*   __restrict__ gt_order,
    const int*   __restrict__ gt_type,
    float* __restrict__ out)
{
    const int b    = blockIdx.x;
    const int seg  = blockIdx.y;
    const int tid  = threadIdx.x;
    const int lane = tid & 31;
    const int w    = tid >> 5;

    __shared__ float2 pgt[NGT];                      // 8 KB
    __shared__ uint32_t skeys[NPRED];                // 4 KB (winner only)
    __shared__ unsigned short tf[NPRED], tb[NPRED];  // 4 KB (winner only)
    __shared__ float rc[8], rs[8], rm[8];
    __shared__ int sflag;

    // ---- pgt = (gt + BOUND)/(2*BOUND), BOUND = {30,15} exact in f32 ----
    const float2* gp2 = reinterpret_cast<const float2*>(gt_pts) + (size_t)b * NGT;
    for (int j = tid; j < NGT; j += TPB) {
        float2 g = gp2[j];
        pgt[j] = make_float2(__fdiv_rn(__fadd_rn(g.x, 30.0f), 60.0f),
                             __fdiv_rn(__fadd_rn(g.y, 15.0f), 30.0f));
    }

    // ---- zero-fill THIS sample's M slice (fire-and-forget) ----
    {
        const size_t s  = (size_t)M_BASE + (size_t)b * NP1 * NP1;
        const size_t e  = s + (size_t)NP1 * NP1;
        const size_t s4 = (s + 3) >> 2, e4 = e >> 2;
        const int tl = seg * TPB + tid;              // 0..16383 within sample
        const float4 z = make_float4(0.f, 0.f, 0.f, 0.f);
        float4* o4 = reinterpret_cast<float4*>(out);
        for (size_t i = s4 + tl; i < e4; i += SEG * TPB) o4[i] = z;
        if (tl == 0) {
            for (size_t i = s; i < (s4 << 2); i++) out[i] = 0.f;
            for (size_t i = (e4 << 2); i < e; i++) out[i] = 0.f;
        }
    }
    __syncthreads();

    // ---- distance: warp handles preds p0, p1; lane covers j = k*32+lane ----
    const int p0 = (seg * 8 + w) * 2;
    const int p1 = p0 + 1;
    const float2 q0 = reinterpret_cast<const float2*>(positions)[(size_t)b * NPRED + p0];
    const float2 q1 = reinterpret_cast<const float2*>(positions)[(size_t)b * NPRED + p1];
    const float px0 = __fdiv_rn(q0.x, 399.0f), py0 = __fdiv_rn(q0.y, 199.0f);
    const float px1 = __fdiv_rn(q1.x, 399.0f), py1 = __fdiv_rn(q1.y, 199.0f);

    float d0 = CUDART_INF_F, d1 = CUDART_INF_F;
    int   a0 = lane, a1 = lane;
    #pragma unroll
    for (int k = 0; k < 32; k++) {
        const int j = k * 32 + lane;
        float2 g = pgt[j];
        float dx, dy, dd;
        dx = __fadd_rn(px0, -g.x); dy = __fadd_rn(py0, -g.y);
        dd = __fadd_rn(__fmul_rn(dx, dx), __fmul_rn(dy, dy));
        if (dd < d0) { d0 = dd; a0 = j; }
        dx = __fadd_rn(px1, -g.x); dy = __fadd_rn(py1, -g.y);
        dd = __fadd_rn(__fmul_rn(dx, dx), __fmul_rn(dy, dy));
        if (dd < d1) { d1 = dd; a1 = j; }
    }
    // warp reduce, exact first-occurrence tie-break (smaller index on ties)
    #pragma unroll
    for (int o = 16; o > 0; o >>= 1) {
        float od = __shfl_down_sync(0xFFFFFFFFu, d0, o);
        int   oa = __shfl_down_sync(0xFFFFFFFFu, a0, o);
        if (od < d0 || (od == d0 && oa < a0)) { d0 = od; a0 = oa; }
        od = __shfl_down_sync(0xFFFFFFFFu, d1, o);
        oa = __shfl_down_sync(0xFFFFFFFFu, a1, o);
        if (od < d1 || (od == d1 && oa < a1)) { d1 = od; a1 = oa; }
    }

    if (lane == 0) {
        const float t0 = 1.5f / 60.0f, t1 = 1.5f / 30.0f;
        const float thr = sqrtf(__fadd_rn(__fmul_rn(t0, t0), __fmul_rn(t1, t1)));
        float cl = 0.f, sl = 0.f;
        #pragma unroll
        for (int h = 0; h < 2; h++) {
            const int   p    = h ? p1 : p0;
            const float dmin = h ? d1 : d0;
            const int   amin = h ? a1 : a0;
            const float px   = h ? px1 : px0;
            const float py   = h ? py1 : py0;
            const bool valid = sqrtf(__fadd_rn(dmin, 1e-12f)) < thr;
            const int gi = gt_ins  [(size_t)b * NGT + amin];
            const int go = gt_order[(size_t)b * NGT + amin];
            const int gc = gt_type [(size_t)b * NGT + amin];
            g_keys[b * NPRED + p] = ((uint32_t)(valid ? (gi + 1) : 0) << 15) |
                                    ((uint32_t)go << 10) | (uint32_t)p;
            float* sgp = out + SG_BASE + (size_t)b * NCLS * NPRED + p;
            sgp[0]         = (gc == 0) ? 1.0f : 0.0f;
            sgp[NPRED]     = (gc == 1) ? 1.0f : 0.0f;
            sgp[2 * NPRED] = (gc == 2) ? 1.0f : 0.0f;
            float2 gn = pgt[amin];
            cl += fabsf(__fadd_rn(px, -gn.x)) + fabsf(__fadd_rn(py, -gn.y));
            sl += semantics[(size_t)b * NCLS * NPRED + (size_t)gc * NPRED + p];
        }
        rc[w] = cl; rs[w] = sl;
    }
    __syncthreads();
    if (tid == 0) {
        float c = 0.f, s = 0.f;
        #pragma unroll
        for (int k = 0; k < 8; k++) { c += rc[k]; s += rs[k]; }
        g_closs  [b * SEG + seg] = c;
        g_semloss[b * SEG + seg] = s;
    }

    // ---- publish + elect per-sample winner (last block to finish) ----
    __threadfence();
    __syncthreads();
    if (tid == 0) {
        int v = atomicAdd(&g_samp_cnt[b], 1);
        sflag = (v == SEG - 1);
        __threadfence();
    }
    __syncthreads();
    if (!sflag) return;

    // ================= winner: sort + edges + M + mloss =================
    for (int i = tid; i < NPRED; i += TPB) {
        skeys[i] = g_keys[b * NPRED + i];
        tf[i] = NPRED; tb[i] = NPRED;
    }
    __syncthreads();

    // bitonic sort, 512 comparators/step, 2 per thread
    for (unsigned k = 2; k <= NPRED; k <<= 1) {
        for (unsigned j = k >> 1; j > 0; j >>= 1) {
            #pragma unroll 2
            for (int c = tid; c < NPRED / 2; c += TPB) {
                int pos = 2 * c - (c & (int)(j - 1));
                int ix  = pos | (int)j;
                uint32_t A = skeys[pos], Bv = skeys[ix];
                bool asc = ((pos & (int)k) == 0);
                if ((A > Bv) == asc) { skeys[pos] = Bv; skeys[ix] = A; }
            }
            __syncthreads();
        }
    }

    // chain edges between consecutive sorted keys with same valid ins
    for (int i = tid; i < NPRED - 1; i += TPB) {
        uint32_t ka = skeys[i], kb = skeys[i + 1];
        uint32_t ga = ka >> 15;
        if (ga == (kb >> 15) && ga != 0) {
            tf[ka & 1023] = (unsigned short)(kb & 1023);
            tb[kb & 1023] = (unsigned short)(ka & 1023);
        }
    }
    __syncthreads();

    const size_t base = (size_t)b * NP1 * NP1;
    float mv = 0.f;
    for (int i = tid; i < NPRED; i += TPB) {
        const int f  = tf[i];
        const int bk = tb[i];
        const size_t row = base + (size_t)i * NP1;
        out[M_BASE + row + f] = 1.0f;                       // M[i][t_fwd] = 1
        if (bk == NPRED)
            out[M_BASE + base + (size_t)NPRED * NP1 + i] = 1.0f;  // M[n][i]
        mv += matches[row + f] + matches[row + bk];
    }
    #pragma unroll
    for (int o = 16; o > 0; o >>= 1)
        mv += __shfl_down_sync(0xFFFFFFFFu, mv, o);
    if (lane == 0) rm[w] = mv;
    __syncthreads();
    if (tid == 0) {
        float m = 0.f;
        #pragma unroll
        for (int k = 0; k < 8; k++) m += rm[k];
        g_mloss[b] = m;
        g_samp_cnt[b] = 0;                 // reset for next graph replay
        __threadfence();
        int v = atomicAdd(&g_done_cnt, 1);
        sflag = (v == BATCH - 1);
        __threadfence();
    }
    __syncthreads();
    if (!sflag) return;

    // ================= final winner: scalar reduction =================
    {
        float c = 0.f, s = 0.f;
        for (int i = tid; i < BATCH * SEG; i += TPB) {  // 4 each, fixed map
            c += g_closs[i]; s += g_semloss[i];
        }
        #pragma unroll
        for (int o = 16; o > 0; o >>= 1) {
            c += __shfl_down_sync(0xFFFFFFFFu, c, o);
            s += __shfl_down_sync(0xFFFFFFFFu, s, o);
        }
        if (lane == 0) { rc[w] = c; rs[w] = s; }
        __syncthreads();
        if (tid == 0) {
            float ct = 0.f, st = 0.f, mt = 0.f;
            #pragma unroll
            for (int k = 0; k < 8; k++) { ct += rc[k]; st += rs[k]; }
            for (int k = 0; k < BATCH; k++) mt += g_mloss[k];
            out[0] =  ct / (float)(BATCH * NPRED * 2);
            out[1] = -mt / (float)(BATCH * NPRED);
            out[2] = -st / (float)(BATCH * NPRED);
            g_done_cnt = 0;                // reset for next graph replay
        }
    }
}

extern "C" void kernel_launch(void* const* d_in, const int* in_sizes, int n_in,
                              void* d_out, int out_size)
{
    const float* matches   = (const float*)d_in[0];
    const float* positions = (const float*)d_in[1];
    const float* semantics = (const float*)d_in[2];
    // d_in[3] = masks (all ones, unused)
    const float* gt_pts    = (const float*)d_in[4];
    const int*   gt_ins    = (const int*)  d_in[5];
    const int*   gt_order  = (const int*)  d_in[6];
    const int*   gt_type   = (const int*)  d_in[7];

    fused<<<dim3(BATCH, SEG), TPB>>>(matches, positions, semantics, gt_pts,
                                     gt_ins, gt_order, gt_type, (float*)d_out);
}

// round 4
// speedup vs baseline: 1.9682x; 1.9682x over previous
#include <cuda_runtime.h>
#include <cstdint>
#include <math_constants.h>

#define BATCH 16
#define NPRED 1024
#define NGT   1024
#define NP1   1025
#define NCLS  3
#define M_BASE 3
#define SEG_A  32          // blocks per sample in phaseA
#define TPB_A  512         // 16 warps; warp = 2 preds -> 32 preds/block
#define SG_BASE (M_BASE + BATCH * NP1 * NP1)

__device__ uint32_t g_keys[BATCH * NPRED];
__device__ float g_closs[BATCH * SEG_A];
__device__ float g_semloss[BATCH * SEG_A];
__device__ float g_mloss[BATCH];
__device__ int   g_done;   // self-resetting ticket for phaseB finalization

// ---------------------------------------------------------------------------
// phaseA: zero-fill M slice + nearest-GT + keys + SG one-hot + closs/semloss
// grid (16, 32) x 512 threads. Warp handles 2 preds; lanes stride the 1024 GT.
// ---------------------------------------------------------------------------
__global__ __launch_bounds__(TPB_A) void phaseA(
    const float* __restrict__ positions,   // (B, N, 2)
    const float* __restrict__ semantics,   // (B, 3, N)
    const float* __restrict__ gt_pts,      // (B, G, 2)
    const int*   __restrict__ gt_ins,
    const int*   __restrict__ gt_order,
    const int*   __restrict__ gt_type,
    float* __restrict__ out)
{
    const int b    = blockIdx.x;
    const int seg  = blockIdx.y;
    const int tid  = threadIdx.x;
    const int lane = tid & 31;
    const int w    = tid >> 5;          // 0..15

    __shared__ float2 pgt[NGT];         // 8 KB
    __shared__ float rc[16], rs[16];

    // pgt = (gt + BOUND)/(2*BOUND); BOUND = {30,15} exact in f32
    const float2* gp2 = reinterpret_cast<const float2*>(gt_pts) + (size_t)b * NGT;
    #pragma unroll
    for (int j = tid; j < NGT; j += TPB_A) {
        float2 g = gp2[j];
        pgt[j] = make_float2(__fdiv_rn(__fadd_rn(g.x, 30.0f), 60.0f),
                             __fdiv_rn(__fadd_rn(g.y, 15.0f), 30.0f));
    }

    // ---- zero-fill THIS sample's M slice (fire-and-forget; drains in L2) ----
    {
        const size_t s  = (size_t)M_BASE + (size_t)b * NP1 * NP1;
        const size_t e  = s + (size_t)NP1 * NP1;
        const size_t s4 = (s + 3) >> 2, e4 = e >> 2;
        const int tl = seg * TPB_A + tid;            // 0..16383 within sample
        const float4 z = make_float4(0.f, 0.f, 0.f, 0.f);
        float4* o4 = reinterpret_cast<float4*>(out);
        for (size_t i = s4 + tl; i < e4; i += SEG_A * TPB_A) o4[i] = z;
        if (tl == 0) {
            for (size_t i = s; i < (s4 << 2); i++) out[i] = 0.f;
            for (size_t i = (e4 << 2); i < e; i++) out[i] = 0.f;
        }
    }
    __syncthreads();

    // ---- distance: warp handles preds p0, p1; lane covers j = k*32+lane ----
    const int p0 = (seg * 16 + w) * 2;
    const int p1 = p0 + 1;
    const float2 q0 = reinterpret_cast<const float2*>(positions)[(size_t)b * NPRED + p0];
    const float2 q1 = reinterpret_cast<const float2*>(positions)[(size_t)b * NPRED + p1];
    const float px0 = __fdiv_rn(q0.x, 399.0f), py0 = __fdiv_rn(q0.y, 199.0f);
    const float px1 = __fdiv_rn(q1.x, 399.0f), py1 = __fdiv_rn(q1.y, 199.0f);

    float d0 = CUDART_INF_F, d1 = CUDART_INF_F;
    int   a0 = lane, a1 = lane;
    #pragma unroll
    for (int k = 0; k < 32; k++) {
        const int j = k * 32 + lane;
        float2 g = pgt[j];
        float dx, dy, dd;
        dx = __fadd_rn(px0, -g.x); dy = __fadd_rn(py0, -g.y);
        dd = __fadd_rn(__fmul_rn(dx, dx), __fmul_rn(dy, dy));
        if (dd < d0) { d0 = dd; a0 = j; }
        dx = __fadd_rn(px1, -g.x); dy = __fadd_rn(py1, -g.y);
        dd = __fadd_rn(__fmul_rn(dx, dx), __fmul_rn(dy, dy));
        if (dd < d1) { d1 = dd; a1 = j; }
    }
    // warp reduce with first-occurrence tie-break (smaller index on ties)
    #pragma unroll
    for (int o = 16; o > 0; o >>= 1) {
        float od = __shfl_down_sync(0xFFFFFFFFu, d0, o);
        int   oa = __shfl_down_sync(0xFFFFFFFFu, a0, o);
        if (od < d0 || (od == d0 && oa < a0)) { d0 = od; a0 = oa; }
        od = __shfl_down_sync(0xFFFFFFFFu, d1, o);
        oa = __shfl_down_sync(0xFFFFFFFFu, a1, o);
        if (od < d1 || (od == d1 && oa < a1)) { d1 = od; a1 = oa; }
    }

    if (lane == 0) {
        const float t0 = 1.5f / 60.0f, t1 = 1.5f / 30.0f;
        const float thr = sqrtf(__fadd_rn(__fmul_rn(t0, t0), __fmul_rn(t1, t1)));
        float cl = 0.f, sl = 0.f;
        #pragma unroll
        for (int h = 0; h < 2; h++) {
            const int   p    = h ? p1 : p0;
            const float dmin = h ? d1 : d0;
            const int   amin = h ? a1 : a0;
            const float px   = h ? px1 : px0;
            const float py   = h ? py1 : py0;
            const bool valid = sqrtf(__fadd_rn(dmin, 1e-12f)) < thr;
            const int gi = gt_ins  [(size_t)b * NGT + amin];
            const int go = gt_order[(size_t)b * NGT + amin];
            const int gc = gt_type [(size_t)b * NGT + amin];
            // sort key: (ins+1)[6b] | order[5b] | idx[10b]
            g_keys[b * NPRED + p] = ((uint32_t)(valid ? (gi + 1) : 0) << 15) |
                                    ((uint32_t)go << 10) | (uint32_t)p;
            float* sgp = out + SG_BASE + (size_t)b * NCLS * NPRED + p;
            sgp[0]         = (gc == 0) ? 1.0f : 0.0f;
            sgp[NPRED]     = (gc == 1) ? 1.0f : 0.0f;
            sgp[2 * NPRED] = (gc == 2) ? 1.0f : 0.0f;
            float2 gn = pgt[amin];
            cl += fabsf(__fadd_rn(px, -gn.x)) + fabsf(__fadd_rn(py, -gn.y));
            sl += semantics[(size_t)b * NCLS * NPRED + (size_t)gc * NPRED + p];
        }
        rc[w] = cl; rs[w] = sl;
    }
    __syncthreads();
    if (tid == 0) {
        float c = 0.f, s = 0.f;
        #pragma unroll
        for (int k = 0; k < 16; k++) { c += rc[k]; s += rs[k]; }
        g_closs  [b * SEG_A + seg] = c;
        g_semloss[b * SEG_A + seg] = s;
    }
}

// ---------------------------------------------------------------------------
// phaseB: per-sample bitonic sort (shuffle for j<32, double-buffered smem for
// j>=32), chain edges, M ones, mloss; last block finalizes the scalars.
// grid 16 x 1024 threads.
// ---------------------------------------------------------------------------
__global__ __launch_bounds__(1024) void phaseB(
    const float* __restrict__ matches,     // (B, 1025, 1025)
    float* __restrict__ out)
{
    const int b = blockIdx.x;
    const int i = threadIdx.x;
    const int lane = i & 31, w = i >> 5;

    __shared__ uint32_t buf[2][NPRED];
    __shared__ unsigned short tf[NPRED], tb[NPRED];
    __shared__ float red[32];
    __shared__ int sflag;

    uint32_t v = g_keys[b * NPRED + i];
    tf[i] = NPRED;
    tb[i] = NPRED;

    int cur = 0;
    for (unsigned k = 2; k <= NPRED; k <<= 1) {
        const bool asc = ((i & k) == 0);
        for (unsigned j = k >> 1; j > 0; j >>= 1) {
            uint32_t pv;
            if (j >= 32) {
                buf[cur][i] = v;
                __syncthreads();
                pv = buf[cur][i ^ j];
                cur ^= 1;
            } else {
                pv = __shfl_xor_sync(0xFFFFFFFFu, v, j);
            }
            const bool lower = ((i & j) == 0);
            uint32_t mn = v < pv ? v : pv;
            uint32_t mx = v < pv ? pv : v;
            v = (lower == asc) ? mn : mx;
        }
    }

    buf[cur][i] = v;
    __syncthreads();

    // chain edges between consecutive sorted keys with same valid ins
    if (i < NPRED - 1) {
        uint32_t ka = buf[cur][i], kb = buf[cur][i + 1];
        uint32_t ga = ka >> 15;
        if (ga == (kb >> 15) && ga != 0) {
            tf[ka & 1023] = (unsigned short)(kb & 1023);
            tb[kb & 1023] = (unsigned short)(ka & 1023);
        }
    }
    __syncthreads();

    const int f  = tf[i];
    const int bk = tb[i];
    const size_t row = (size_t)b * NP1 * NP1 + (size_t)i * NP1;

    out[M_BASE + row + f] = 1.0f;                            // M[i][t_fwd]=1
    if (bk == NPRED)
        out[M_BASE + (size_t)b * NP1 * NP1 + (size_t)NPRED * NP1 + i] = 1.0f;

    float mv = matches[row + f] + matches[row + bk];

    #pragma unroll
    for (int o = 16; o > 0; o >>= 1)
        mv += __shfl_down_sync(0xFFFFFFFFu, mv, o);
    if (lane == 0) red[w] = mv;
    __syncthreads();

    if (i == 0) {
        float m = 0.f;
        #pragma unroll
        for (int k = 0; k < 32; k++) m += red[k];
        g_mloss[b] = m;
        __threadfence();                     // tiny: one float + flag
        int t = atomicAdd(&g_done, 1);
        sflag = (t == BATCH - 1);
        __threadfence();
    }
    __syncthreads();
    if (!sflag) return;

    // ---- last block: final scalar reduction (deterministic fixed order) ----
    {
        float c = 0.f, s = 0.f;
        if (i < BATCH * SEG_A) { c = g_closs[i]; s = g_semloss[i]; }  // 512 vals
        #pragma unroll
        for (int o = 16; o > 0; o >>= 1) {
            c += __shfl_down_sync(0xFFFFFFFFu, c, o);
            s += __shfl_down_sync(0xFFFFFFFFu, s, o);
        }
        __shared__ float rc2[32], rs2[32];
        if (lane == 0) { rc2[w] = c; rs2[w] = s; }
        __syncthreads();
        if (i == 0) {
            float ct = 0.f, st = 0.f, mt = 0.f;
            #pragma unroll
            for (int k = 0; k < 16; k++) { ct += rc2[k]; st += rs2[k]; }
            #pragma unroll
            for (int k = 0; k < BATCH; k++) mt += g_mloss[k];
            out[0] =  ct / (float)(BATCH * NPRED * 2);
            out[1] = -mt / (float)(BATCH * NPRED);
            out[2] = -st / (float)(BATCH * NPRED);
            g_done = 0;                      // reset for next graph replay
        }
    }
}

extern "C" void kernel_launch(void* const* d_in, const int* in_sizes, int n_in,
                              void* d_out, int out_size)
{
    const float* matches   = (const float*)d_in[0];
    const float* positions = (const float*)d_in[1];
    const float* semantics = (const float*)d_in[2];
    // d_in[3] = masks (all ones, unused)
    const float* gt_pts    = (const float*)d_in[4];
    const int*   gt_ins    = (const int*)  d_in[5];
    const int*   gt_order  = (const int*)  d_in[6];
    const int*   gt_type   = (const int*)  d_in[7];
    float* out = (float*)d_out;

    phaseA<<<dim3(BATCH, SEG_A), TPB_A>>>(positions, semantics, gt_pts,
                                          gt_ins, gt_order, gt_type, out);
    phaseB<<<BATCH, NPRED>>>(matches, out);
}